// round 9
// baseline (speedup 1.0000x reference)
#include <cuda_runtime.h>
#include <cuda_fp16.h>
#include <math.h>

#define NB   4
#define CH   16
#define HWSZ 65536
#define EPSV 1e-6f
#define LOG2E_T 14.4269504089f     // (1/TEMP) * log2(e)
#define LN2F    0.69314718056f

typedef unsigned long long u64;
typedef unsigned int u32;

// Channels-last normalized features in fp16: [n][pix][16 halves] = 8 MB
__device__ u32 g_fnh[(size_t)NB * HWSZ * 8];
__device__ float g_lp[256];
__device__ float g_dp[1024];
__device__ unsigned int g_ctr = 0;

// ---------------- helpers ----------------
__device__ __forceinline__ u64 f2add(u64 a, u64 b) {
    u64 d; asm("add.rn.f32x2 %0,%1,%2;" : "=l"(d) : "l"(a), "l"(b)); return d;
}
__device__ __forceinline__ u64 pack2(float lo, float hi) {
    u64 d; asm("mov.b64 %0,{%1,%2};" : "=l"(d) : "f"(lo), "f"(hi)); return d;
}
__device__ __forceinline__ void unpack2(u64 v, float& lo, float& hi) {
    asm("mov.b64 {%0,%1},%2;" : "=f"(lo), "=f"(hi) : "l"(v));
}
__device__ __forceinline__ float ex2f(float x) {
    float r; asm("ex2.approx.ftz.f32 %0,%1;" : "=f"(r) : "f"(x)); return r;
}
// fp16 (half2) 16-dim dot: 8 HFMA2 in 2 chains, join, fold, 1 convert
__device__ __forceinline__ float dot16h(const u32 a[8], const u32 b[8]) {
    u32 p, q, r, rs, r2;
    asm("mul.rn.f16x2 %0,%1,%2;" : "=r"(p) : "r"(a[0]), "r"(b[0]));
    asm("mul.rn.f16x2 %0,%1,%2;" : "=r"(q) : "r"(a[1]), "r"(b[1]));
    asm("fma.rn.f16x2 %0,%1,%2,%3;" : "=r"(p) : "r"(a[2]), "r"(b[2]), "r"(p));
    asm("fma.rn.f16x2 %0,%1,%2,%3;" : "=r"(q) : "r"(a[3]), "r"(b[3]), "r"(q));
    asm("fma.rn.f16x2 %0,%1,%2,%3;" : "=r"(p) : "r"(a[4]), "r"(b[4]), "r"(p));
    asm("fma.rn.f16x2 %0,%1,%2,%3;" : "=r"(q) : "r"(a[5]), "r"(b[5]), "r"(q));
    asm("fma.rn.f16x2 %0,%1,%2,%3;" : "=r"(p) : "r"(a[6]), "r"(b[6]), "r"(p));
    asm("fma.rn.f16x2 %0,%1,%2,%3;" : "=r"(q) : "r"(a[7]), "r"(b[7]), "r"(q));
    asm("add.rn.f16x2 %0,%1,%2;" : "=r"(r) : "r"(p), "r"(q));
    asm("prmt.b32 %0,%1,%1,0x1032;" : "=r"(rs) : "r"(r));
    asm("add.rn.f16x2 %0,%1,%2;" : "=r"(r2) : "r"(r), "r"(rs));
    float f;
    asm("{.reg .b16 lo,hi; mov.b32 {lo,hi}, %1; cvt.f32.f16 %0, lo;}"
        : "=f"(f) : "r"(r2));
    return f;
}
// scale 8 half2 regs by splat constant (fp16)
__device__ __forceinline__ void scale16h(u32 h[8], u32 k2) {
#pragma unroll
    for (int i = 0; i < 8; i++)
        asm("mul.rn.f16x2 %0,%1,%2;" : "=r"(h[i]) : "r"(h[i]), "r"(k2));
}
// load 16 halves (as 8 u32) from a parity sub-array with XOR swizzle
__device__ __forceinline__ void load16h(const char* base, int idx, u32 h[8]) {
    int sw = ((idx >> 2) & 1) << 4;
    const char* p = base + (idx << 5);
    uint4 a = *(const uint4*)(p + sw);
    uint4 b = *(const uint4*)(p + (16 ^ sw));
    h[0]=a.x; h[1]=a.y; h[2]=a.z; h[3]=a.w;
    h[4]=b.x; h[5]=b.y; h[6]=b.z; h[7]=b.w;
}

// ---------------------------------------------------------------------------
// Kernel 1: L2-normalize + transpose + fp16 quantize. 1 pixel/thread.
// ---------------------------------------------------------------------------
__global__ void __launch_bounds__(256)
k_norm(const float* __restrict__ f) {
    int idx = blockIdx.x * 256 + threadIdx.x;  // 0 .. N*HW-1
    int n   = idx >> 16;
    int pix = idx & 65535;
    const float* b = f + (size_t)n * CH * HWSZ + pix;
    float v[CH];
    float ss = 0.f;
#pragma unroll
    for (int c = 0; c < CH; c++) {
        v[c] = b[(size_t)c * HWSZ];
        ss = fmaf(v[c], v[c], ss);
    }
    float inv = 1.0f / fmaxf(sqrtf(ss), 1e-12f);
    u32 h[8];
#pragma unroll
    for (int c2 = 0; c2 < 8; c2++) {
        __half2 hh = __floats2half2_rn(v[c2*2] * inv, v[c2*2+1] * inv);
        h[c2] = *(u32*)&hh;
    }
    uint4* o = (uint4*)(g_fnh + (size_t)idx * 8);
    o[0] = make_uint4(h[0], h[1], h[2], h[3]);
    o[1] = make_uint4(h[4], h[5], h[6], h[7]);
}

// ---------------------------------------------------------------------------
// Fused main kernel.
// Blocks [0,256):    local 11x11 term. Tile = 16 rows x 64 cols, 256 threads,
//                    2x2 quad per thread. Halo 26 rows x 76 cols -> 69.5 KB
//                    smem, 3 blocks/SM (6 warps/SMSP), single wave.
// Blocks [256,1280): directional term (fills the local wave's tail).
// Last-finishing block does the deterministic final sum.
// ---------------------------------------------------------------------------
#define ROWB 2432                    // 76 px * 32 B (38 even | 38 odd)
#define HOFF 1216                    // odd-parity sub-array offset
__global__ void __launch_bounds__(256, 3)
k_main(const int* __restrict__ labels, const int* __restrict__ dirs,
       float* __restrict__ out) {
    extern __shared__ char sm[];
    const int bx = blockIdx.x;
    const int t  = threadIdx.x;
    float val;

    if (bx < 256) {
        // ================= LOCAL PART =================
        char* sF   = sm;                      // 26 * 2432 = 63232 B
        int*  sLab = (int*)(sm + 26 * ROWB);  // 26 * 76 ints = 7904 B

        const int n   = bx >> 6;
        const int rem = bx & 63;
        const int i0  = (rem >> 2) << 4;      // first center row (mult of 16)
        const int q   = rem & 3;              // 64-col quarter
        const int j0  = q << 6;
        const int cb  = j0 - 6;               // halo base col

        // ---- fill halo: 26 rows x 76 cols ----
        {
            const uint4* src = (const uint4*)(g_fnh + (size_t)n * HWSZ * 8);
#pragma unroll
            for (int k = 0; k < 16; k++) {
                int lin = t + (k << 8);           // need 3952
                if (lin < 3952) {
                    int rr = lin / 152;
                    int w  = lin - rr * 152;
                    int ch = w & 1;
                    int x  = w >> 1;              // tile col 0..75
                    int row = i0 - 5 + rr;
                    int g   = cb + x;
                    if ((unsigned)row < 256u && (unsigned)g < 256u) {
                        uint4 v = src[(size_t)((row << 8) + g) * 2 + ch];
                        int e = x >> 1;
                        *(uint4*)(sF + rr * ROWB + (x & 1) * HOFF + (e << 5)
                                  + ((ch ^ ((e >> 2) & 1)) << 4)) = v;
                    }
                }
            }
            const int* ls = labels + n * HWSZ;
#pragma unroll
            for (int k = 0; k < 8; k++) {
                int lin = t + (k << 8);           // need 1976
                if (lin < 1976) {
                    int rr = lin / 76;
                    int x  = lin - rr * 76;
                    int row = i0 - 5 + rr;
                    int g   = cb + x;
                    bool ok = ((unsigned)row < 256u) && ((unsigned)g < 256u);
                    sLab[rr * 76 + (x & 1) * 38 + (x >> 1)] =
                        ok ? ls[(row << 8) + g] : (int)0x80000000;
                }
            }
        }
        __syncthreads();

        const int rp = t >> 5;               // 0..7 (warp-uniform)
        const int cp = t & 31;               // col pair 0..31
        const int tc = cp + 3;               // center parity index
        const int sA = 2 * rp + 5;
        const int sB = sA + 1;

        u32 cvAe[8], cvAo[8], cvBe[8], cvBo[8];
        load16h(sF + sA * ROWB,        tc, cvAe);
        load16h(sF + sA * ROWB + HOFF, tc, cvAo);
        load16h(sF + sB * ROWB,        tc, cvBe);
        load16h(sF + sB * ROWB + HOFF, tc, cvBo);
        __half2 kt = __floats2half2_rn(LOG2E_T, LOG2E_T);
        u32 kt2 = *(u32*)&kt;
        scale16h(cvAe, kt2); scale16h(cvAo, kt2);
        scale16h(cvBe, kt2); scale16h(cvBo, kt2);
        const int clAe = sLab[sA * 76 + tc];
        const int clAo = sLab[sA * 76 + 38 + tc];
        const int clBe = sLab[sB * 76 + tc];
        const int clBo = sLab[sB * 76 + 38 + tc];

        u64 SDAe = 0, SDAo = 0, SDBe = 0, SDBo = 0;   // packed {S, D}
        int MAe = 0, MAo = 0, MBe = 0, MBo = 0;

#pragma unroll 1
        for (int v = 0; v < 12; v++) {
            int s   = 2 * rp + v;
            int row = i0 - 5 + s;
            if ((unsigned)row >= 256u) continue;   // warp-uniform
            const bool rokA = (v <= 10);
            const bool rokB = (v >= 1);
            const char* rowE = sF + s * ROWB;
            const char* rowO = rowE + HOFF;
            const int* labE = sLab + s * 76;
            const int* labO = labE + 38;

            // even-pixel neighbors: e = cp+1+u
#pragma unroll
            for (int u = 0; u < 6; u++) {
                int e  = cp + 1 + u;
                int gx = cb + (e << 1);
                bool vld = (unsigned)gx < 256u;
                u32 nv[8]; load16h(rowE, e, nv);
                int lb = labE[e];
                {
                    float dAo = dot16h(cvAo, nv);      // already log2-scaled
                    float dBo = dot16h(cvBo, nv);
                    float eA = ex2f(dAo), eB = ex2f(dBo);
                    if (vld && rokA && lb == clAo) { SDAo = f2add(SDAo, pack2(eA, dAo)); MAo++; }
                    if (vld && rokB && lb == clBo) { SDBo = f2add(SDBo, pack2(eB, dBo)); MBo++; }
                }
                if (u != 5) {
                    float dAe = dot16h(cvAe, nv);
                    float dBe = dot16h(cvBe, nv);
                    float eA = ex2f(dAe), eB = ex2f(dBe);
                    if (vld && rokA && lb == clAe) { SDAe = f2add(SDAe, pack2(eA, dAe)); MAe++; }
                    if (vld && rokB && lb == clBe) { SDBe = f2add(SDBe, pack2(eB, dBe)); MBe++; }
                }
            }
            // odd-pixel neighbors: o = cp+u
#pragma unroll
            for (int u = 0; u < 6; u++) {
                int o  = cp + u;
                int gx = cb + (o << 1) + 1;
                bool vld = (unsigned)gx < 256u;
                u32 nv[8]; load16h(rowO, o, nv);
                int lb = labO[o];
                {
                    float dAe = dot16h(cvAe, nv);
                    float dBe = dot16h(cvBe, nv);
                    float eA = ex2f(dAe), eB = ex2f(dBe);
                    if (vld && rokA && lb == clAe) { SDAe = f2add(SDAe, pack2(eA, dAe)); MAe++; }
                    if (vld && rokB && lb == clBe) { SDBe = f2add(SDBe, pack2(eB, dBe)); MBe++; }
                }
                if (u != 0) {
                    float dAo = dot16h(cvAo, nv);
                    float dBo = dot16h(cvBo, nv);
                    float eA = ex2f(dAo), eB = ex2f(dBo);
                    if (vld && rokA && lb == clAo) { SDAo = f2add(SDAo, pack2(eA, dAo)); MAo++; }
                    if (vld && rokB && lb == clBo) { SDBo = f2add(SDBo, pack2(eB, dBo)); MBo++; }
                }
            }
        }

        float SAe, DAe, SAo, DAo, SBe, DBe, SBo, DBo;
        unpack2(SDAe, SAe, DAe);  unpack2(SDAo, SAo, DAo);
        unpack2(SDBe, SBe, DBe);  unpack2(SDBo, SBo, DBo);

        float cAe = fmaf((float)MAe, __logf(SAe + EPSV), -LN2F * DAe);
        float cAo = fmaf((float)MAo, __logf(SAo + EPSV), -LN2F * DAo);
        float cBe = fmaf((float)MBe, __logf(SBe + EPSV), -LN2F * DBe);
        float cBo = fmaf((float)MBo, __logf(SBo + EPSV), -LN2F * DBo);
        int ciA = i0 + 2 * rp, ciB = ciA + 1;
        int jc0 = j0 + 2 * cp, jc1 = jc0 + 1;
        float chA = (float)(11 - max(0, 5 - ciA) - max(0, ciA - 250));
        float chB = (float)(11 - max(0, 5 - ciB) - max(0, ciB - 250));
        float cw0 = (float)(11 - max(0, 5 - jc0) - max(0, jc0 - 250));
        float cw1 = (float)(11 - max(0, 5 - jc1) - max(0, jc1 - 250));
        val = (cAe / (chA * cw0) + cAo / (chA * cw1)
             + cBe / (chB * cw0) + cBo / (chB * cw1)) * (1.0f / (4.0f * 65536.0f));
    } else {
        // ================= DIRECTIONAL PART =================
        const int dbx = bx - 256;                   // 0..1023
        const int idx = dbx * 256 + t;              // 0..262143
        const int nn  = idx >> 16;
        const int pix = idx & 65535;
        const int i = pix >> 8, j = pix & 255;

        int off[NB], lc[NB];
#pragma unroll
        for (int k = 0; k < NB; k++) {
            int dik = dirs[(k * 2 + 0) * HWSZ + pix];
            int djk = dirs[(k * 2 + 1) * HWSZ + pix];
            off[k] = ((i + dik) << 8) + (j + djk);
            lc[k]  = labels[k * HWSZ + pix];
        }

        const uint4* base = (const uint4*)(g_fnh + (size_t)nn * HWSZ * 8);
        u32 cv[8];
        {
            uint4 a = base[(size_t)pix * 2], b = base[(size_t)pix * 2 + 1];
            cv[0]=a.x; cv[1]=a.y; cv[2]=a.z; cv[3]=a.w;
            cv[4]=b.x; cv[5]=b.y; cv[6]=b.z; cv[7]=b.w;
        }
        __half2 kt = __floats2half2_rn(LOG2E_T, LOG2E_T);
        scale16h(cv, *(u32*)&kt);

        float dt[NB]; bool mk[NB]; float S = 0.f;
#pragma unroll
        for (int k = 0; k < NB; k++) {
            u32 nv[8];
            uint4 a = base[(size_t)off[k] * 2], b = base[(size_t)off[k] * 2 + 1];
            nv[0]=a.x; nv[1]=a.y; nv[2]=a.z; nv[3]=a.w;
            nv[4]=b.x; nv[5]=b.y; nv[6]=b.z; nv[7]=b.w;
            dt[k] = dot16h(cv, nv);                 // log2-scaled logit
            mk[k] = (labels[nn * HWSZ + off[k]] == lc[k]);
            S += mk[k] ? ex2f(dt[k]) : 0.f;
        }
        float logS = __logf(S + EPSV);
        float sum = 0.f;
#pragma unroll
        for (int k = 0; k < NB; k++)
            sum += mk[k] ? (logS - LN2F * dt[k]) : __int_as_float(0x7f800000);
        val = sum * (1.0f / (16.0f * 65536.0f));
    }

    // ---------------- common tail: block reduce + last-block final sum ------
    __shared__ float wred[8];
    __shared__ bool  slast;
#pragma unroll
    for (int o = 16; o > 0; o >>= 1) val += __shfl_down_sync(0xffffffffu, val, o);
    if ((t & 31) == 0) wred[t >> 5] = val;
    __syncthreads();
    if (t < 32) {
        float x = (t < 8) ? wred[t] : 0.f;
#pragma unroll
        for (int o = 4; o > 0; o >>= 1) x += __shfl_down_sync(0xffffffffu, x, o);
        if (t == 0) {
            if (bx < 256) g_lp[bx] = x;
            else          g_dp[bx - 256] = x;
            __threadfence();
            unsigned old = atomicAdd(&g_ctr, 1u);
            slast = (old == 1279u);
        }
    }
    __syncthreads();

    if (slast) {   // deterministic final reduction
        float v = g_lp[t]
                + g_dp[t] + g_dp[t + 256] + g_dp[t + 512] + g_dp[t + 768];
#pragma unroll
        for (int o = 16; o > 0; o >>= 1) v += __shfl_down_sync(0xffffffffu, v, o);
        if ((t & 31) == 0) wred[t >> 5] = v;
        __syncthreads();
        if (t == 0) {
            float s = 0.f;
#pragma unroll
            for (int w = 0; w < 8; w++) s += wred[w];
            out[0] = s;
            g_ctr = 0;   // reset for next graph replay
        }
    }
}

// ---------------------------------------------------------------------------
extern "C" void kernel_launch(void* const* d_in, const int* in_sizes, int n_in,
                              void* d_out, int out_size) {
    const float* feat   = (const float*)d_in[0];
    const int*   labels = (const int*)d_in[1];
    const int*   dirs   = (const int*)d_in[2];
    float* out = (float*)d_out;

    const int smem = 26 * ROWB + 26 * 76 * 4;   // 63232 + 7904 = 71136 B
    cudaFuncSetAttribute(k_main, cudaFuncAttributeMaxDynamicSharedMemorySize, smem);

    k_norm<<<1024, 256>>>(feat);
    k_main<<<1280, 256, smem>>>(labels, dirs, out);
}

// round 10
// speedup vs baseline: 1.3633x; 1.3633x over previous
#include <cuda_runtime.h>
#include <cuda_fp16.h>
#include <math.h>

#define NB   4
#define CH   16
#define HWSZ 65536
#define EPSV 1e-6f
#define LOG2E_T 14.4269504089f     // (1/TEMP) * log2(e)
#define LN2F    0.69314718056f

typedef unsigned long long u64;
typedef unsigned int u32;

// Channels-last normalized features in fp16: [n][pix][16 halves] = 8 MB
__device__ u32 g_fnh[(size_t)NB * HWSZ * 8];
__device__ float g_lp[512];
__device__ unsigned int g_ctr = 0;

// ---------------- helpers ----------------
__device__ __forceinline__ u64 f2add(u64 a, u64 b) {
    u64 d; asm("add.rn.f32x2 %0,%1,%2;" : "=l"(d) : "l"(a), "l"(b)); return d;
}
__device__ __forceinline__ u64 pack2(float lo, float hi) {
    u64 d; asm("mov.b64 %0,{%1,%2};" : "=l"(d) : "f"(lo), "f"(hi)); return d;
}
__device__ __forceinline__ void unpack2(u64 v, float& lo, float& hi) {
    asm("mov.b64 {%0,%1},%2;" : "=f"(lo), "=f"(hi) : "l"(v));
}
__device__ __forceinline__ float ex2f(float x) {
    float r; asm("ex2.approx.ftz.f32 %0,%1;" : "=f"(r) : "f"(x)); return r;
}
// fp16 (half2) 16-dim dot: 8 HFMA2 in 2 chains, join, fold, 1 convert
__device__ __forceinline__ float dot16h(const u32 a[8], const u32 b[8]) {
    u32 p, q, r, rs, r2;
    asm("mul.rn.f16x2 %0,%1,%2;" : "=r"(p) : "r"(a[0]), "r"(b[0]));
    asm("mul.rn.f16x2 %0,%1,%2;" : "=r"(q) : "r"(a[1]), "r"(b[1]));
    asm("fma.rn.f16x2 %0,%1,%2,%3;" : "=r"(p) : "r"(a[2]), "r"(b[2]), "r"(p));
    asm("fma.rn.f16x2 %0,%1,%2,%3;" : "=r"(q) : "r"(a[3]), "r"(b[3]), "r"(q));
    asm("fma.rn.f16x2 %0,%1,%2,%3;" : "=r"(p) : "r"(a[4]), "r"(b[4]), "r"(p));
    asm("fma.rn.f16x2 %0,%1,%2,%3;" : "=r"(q) : "r"(a[5]), "r"(b[5]), "r"(q));
    asm("fma.rn.f16x2 %0,%1,%2,%3;" : "=r"(p) : "r"(a[6]), "r"(b[6]), "r"(p));
    asm("fma.rn.f16x2 %0,%1,%2,%3;" : "=r"(q) : "r"(a[7]), "r"(b[7]), "r"(q));
    asm("add.rn.f16x2 %0,%1,%2;" : "=r"(r) : "r"(p), "r"(q));
    asm("prmt.b32 %0,%1,%1,0x1032;" : "=r"(rs) : "r"(r));
    asm("add.rn.f16x2 %0,%1,%2;" : "=r"(r2) : "r"(r), "r"(rs));
    float f;
    asm("{.reg .b16 lo,hi; mov.b32 {lo,hi}, %1; cvt.f32.f16 %0, lo;}"
        : "=f"(f) : "r"(r2));
    return f;
}
// scale 8 half2 regs by splat constant (fp16)
__device__ __forceinline__ void scale16h(u32 h[8], u32 k2) {
#pragma unroll
    for (int i = 0; i < 8; i++)
        asm("mul.rn.f16x2 %0,%1,%2;" : "=r"(h[i]) : "r"(h[i]), "r"(k2));
}
// load 16 halves (as 8 u32) from a parity sub-array with XOR swizzle
__device__ __forceinline__ void load16h(const char* base, int idx, u32 h[8]) {
    int sw = ((idx >> 2) & 1) << 4;
    const char* p = base + (idx << 5);
    uint4 a = *(const uint4*)(p + sw);
    uint4 b = *(const uint4*)(p + (16 ^ sw));
    h[0]=a.x; h[1]=a.y; h[2]=a.z; h[3]=a.w;
    h[4]=b.x; h[5]=b.y; h[6]=b.z; h[7]=b.w;
}

#define ROWB 2560                    // bytes per row slot (40+40 vecs of 32B)
#define HOFF 1280                    // odd-parity sub-array offset

// ---- directional term for ONE center pixel (neighbors are a 3x3 stencil,
//      entirely inside the halo tile) ----
__device__ __forceinline__ float dirterm(const char* sF, const int* sLab,
                                         const int* __restrict__ labels,
                                         const int* __restrict__ dirs,
                                         const u32 cv[8], int srow, int xc,
                                         int pix) {
    float dt[NB]; bool mk[NB]; float S = 0.f;
#pragma unroll
    for (int k = 0; k < NB; k++) {
        int dik = dirs[(k * 2 + 0) * HWSZ + pix];
        int djk = dirs[(k * 2 + 1) * HWSZ + pix];
        int sl = srow + dik;                 // halo row slot (always in range)
        int x  = xc + djk;                   // tile col (always in range)
        u32 nv[8]; load16h(sF + sl * ROWB + (x & 1) * HOFF, x >> 1, nv);
        dt[k] = dot16h(cv, nv);              // log2-scaled logit
        int lbn = sLab[sl * 80 + (x & 1) * 40 + (x >> 1)];
        mk[k] = (labels[k * HWSZ + pix] == lbn);
        S += mk[k] ? ex2f(dt[k]) : 0.f;
    }
    float logS = __logf(S + EPSV);
    float s = 0.f;
#pragma unroll
    for (int k = 0; k < NB; k++)
        s += mk[k] ? (logS - LN2F * dt[k]) : __int_as_float(0x7f800000);
    return s;
}

// ---------------------------------------------------------------------------
// Kernel 1: L2-normalize + transpose + fp16 quantize. 1 pixel/thread.
// ---------------------------------------------------------------------------
__global__ void __launch_bounds__(256)
k_norm(const float* __restrict__ f) {
    int idx = blockIdx.x * 256 + threadIdx.x;  // 0 .. N*HW-1
    int n   = idx >> 16;
    int pix = idx & 65535;
    const float* b = f + (size_t)n * CH * HWSZ + pix;
    float v[CH];
    float ss = 0.f;
#pragma unroll
    for (int c = 0; c < CH; c++) {
        v[c] = b[(size_t)c * HWSZ];
        ss = fmaf(v[c], v[c], ss);
    }
    float inv = 1.0f / fmaxf(sqrtf(ss), 1e-12f);
    u32 h[8];
#pragma unroll
    for (int c2 = 0; c2 < 8; c2++) {
        __half2 hh = __floats2half2_rn(v[c2*2] * inv, v[c2*2+1] * inv);
        h[c2] = *(u32*)&hh;
    }
    uint4* o = (uint4*)(g_fnh + (size_t)idx * 8);
    o[0] = make_uint4(h[0], h[1], h[2], h[3]);
    o[1] = make_uint4(h[4], h[5], h[6], h[7]);
}

// ---------------------------------------------------------------------------
// Kernel 2: local 11x11 term + directional term, fused per-pixel.
// Block = (n, 8 center rows, 64-col quarter). 128 threads, 2x2 quad per
// thread. Halo 18 rows x 80 cols, fp16 channels-last, even/odd parity split
// + XOR swizzle. 51.8 KB smem -> 4 blocks/SM. Last block: final sum.
// ---------------------------------------------------------------------------
__global__ void __launch_bounds__(128, 4)
k_local(const int* __restrict__ labels, const int* __restrict__ dirs,
        float* __restrict__ out) {
    extern __shared__ char sm[];
    char* sF   = sm;                      // 18 * 2560 = 46080 B
    int*  sLab = (int*)(sm + 18 * ROWB);  // 18 * 80 ints = 5760 B

    const int bx  = blockIdx.x;           // 0..511
    const int n   = bx >> 7;
    const int rem = bx & 127;
    const int i0  = (rem >> 2) << 3;      // first center row (mult of 8)
    const int hq  = rem & 3;              // which 64-col quarter
    const int cb  = hq * 64 - 8;          // tile base col (global)
    const int t   = threadIdx.x;

    // ---- fill halo: 18 rows x 80 cols ----
    {
        const uint4* src = (const uint4*)(g_fnh + (size_t)n * HWSZ * 8);
#pragma unroll
        for (int k = 0; k < 23; k++) {
            int lin = t + (k << 7);           // need 2880
            if (lin < 2880) {
                int rr = lin / 160;
                int w  = lin - rr * 160;
                int ch = w & 1;
                int x  = w >> 1;              // tile col 0..79
                int row = i0 - 5 + rr;
                int g   = cb + x;
                if ((unsigned)row < 256u && (unsigned)g < 256u) {
                    uint4 v = src[(size_t)((row << 8) + g) * 2 + ch];
                    int parity = x & 1, e = x >> 1;
                    *(uint4*)(sF + rr * ROWB + parity * HOFF + (e << 5)
                              + ((ch ^ ((e >> 2) & 1)) << 4)) = v;
                }
            }
        }
        const int* ls = labels + n * HWSZ;
#pragma unroll
        for (int k = 0; k < 12; k++) {
            int lin = t + (k << 7);           // need 1440
            if (lin < 1440) {
                int rr = lin / 80;
                int x  = lin - rr * 80;
                int row = i0 - 5 + rr;
                int g   = cb + x;
                bool ok = ((unsigned)row < 256u) && ((unsigned)g < 256u);
                sLab[rr * 80 + (x & 1) * 40 + (x >> 1)] =
                    ok ? ls[(row << 8) + g] : (int)0x80000000;
            }
        }
    }
    __syncthreads();

    const int rp = t >> 5;               // 0..3 (warp-uniform)
    const int cp = t & 31;
    const int tc = cp + 4;
    const int sA = 2 * rp + 5;
    const int sB = sA + 1;

    u32 cvAe[8], cvAo[8], cvBe[8], cvBo[8];
    load16h(sF + sA * ROWB,        tc, cvAe);
    load16h(sF + sA * ROWB + HOFF, tc, cvAo);
    load16h(sF + sB * ROWB,        tc, cvBe);
    load16h(sF + sB * ROWB + HOFF, tc, cvBo);
    __half2 kt = __floats2half2_rn(LOG2E_T, LOG2E_T);
    u32 kt2 = *(u32*)&kt;
    scale16h(cvAe, kt2); scale16h(cvAo, kt2);
    scale16h(cvBe, kt2); scale16h(cvBo, kt2);
    const int clAe = sLab[sA * 80 + tc];
    const int clAo = sLab[sA * 80 + 40 + tc];
    const int clBe = sLab[sB * 80 + tc];
    const int clBo = sLab[sB * 80 + 40 + tc];

    u64 SDAe = 0, SDAo = 0, SDBe = 0, SDBo = 0;   // packed {S, D}
    int MAe = 0, MAo = 0, MBe = 0, MBo = 0;

#pragma unroll 1
    for (int v = 0; v < 12; v++) {
        int s   = 2 * rp + v;
        int row = i0 - 5 + s;
        if ((unsigned)row >= 256u) continue;   // warp-uniform
        const bool rokA = (v <= 10);
        const bool rokB = (v >= 1);
        const char* rowE = sF + s * ROWB;
        const char* rowO = rowE + HOFF;
        const int* labE = sLab + s * 80;
        const int* labO = labE + 40;

        // even-pixel neighbors
#pragma unroll
        for (int u = 0; u < 6; u++) {
            int e  = cp + 2 + u;
            int gx = cb + (e << 1);
            bool vld = (unsigned)gx < 256u;
            u32 nv[8]; load16h(rowE, e, nv);
            int lb = labE[e];
            {
                float dAo = dot16h(cvAo, nv);      // already log2-scaled
                float dBo = dot16h(cvBo, nv);
                float eA = ex2f(dAo), eB = ex2f(dBo);
                if (vld && rokA && lb == clAo) { SDAo = f2add(SDAo, pack2(eA, dAo)); MAo++; }
                if (vld && rokB && lb == clBo) { SDBo = f2add(SDBo, pack2(eB, dBo)); MBo++; }
            }
            if (u != 5) {
                float dAe = dot16h(cvAe, nv);
                float dBe = dot16h(cvBe, nv);
                float eA = ex2f(dAe), eB = ex2f(dBe);
                if (vld && rokA && lb == clAe) { SDAe = f2add(SDAe, pack2(eA, dAe)); MAe++; }
                if (vld && rokB && lb == clBe) { SDBe = f2add(SDBe, pack2(eB, dBe)); MBe++; }
            }
        }
        // odd-pixel neighbors
#pragma unroll
        for (int u = 0; u < 6; u++) {
            int o  = cp + 1 + u;
            int gx = cb + (o << 1) + 1;
            bool vld = (unsigned)gx < 256u;
            u32 nv[8]; load16h(rowO, o, nv);
            int lb = labO[o];
            {
                float dAe = dot16h(cvAe, nv);
                float dBe = dot16h(cvBe, nv);
                float eA = ex2f(dAe), eB = ex2f(dBe);
                if (vld && rokA && lb == clAe) { SDAe = f2add(SDAe, pack2(eA, dAe)); MAe++; }
                if (vld && rokB && lb == clBe) { SDBe = f2add(SDBe, pack2(eB, dBe)); MBe++; }
            }
            if (u != 0) {
                float dAo = dot16h(cvAo, nv);
                float dBo = dot16h(cvBo, nv);
                float eA = ex2f(dAo), eB = ex2f(dBo);
                if (vld && rokA && lb == clAo) { SDAo = f2add(SDAo, pack2(eA, dAo)); MAo++; }
                if (vld && rokB && lb == clBo) { SDBo = f2add(SDBo, pack2(eB, dBo)); MBo++; }
            }
        }
    }

    float SAe, DAe, SAo, DAo, SBe, DBe, SBo, DBo;
    unpack2(SDAe, SAe, DAe);  unpack2(SDAo, SAo, DAo);
    unpack2(SDBe, SBe, DBe);  unpack2(SDBo, SBo, DBo);

    float cAe = fmaf((float)MAe, __logf(SAe + EPSV), -LN2F * DAe);
    float cAo = fmaf((float)MAo, __logf(SAo + EPSV), -LN2F * DAo);
    float cBe = fmaf((float)MBe, __logf(SBe + EPSV), -LN2F * DBe);
    float cBo = fmaf((float)MBo, __logf(SBo + EPSV), -LN2F * DBo);
    int ciA = i0 + 2 * rp, ciB = ciA + 1;
    int j0  = hq * 64 + 2 * cp, j1 = j0 + 1;
    float chA = (float)(11 - max(0, 5 - ciA) - max(0, ciA - 250));
    float chB = (float)(11 - max(0, 5 - ciB) - max(0, ciB - 250));
    float cw0 = (float)(11 - max(0, 5 - j0)  - max(0, j0  - 250));
    float cw1 = (float)(11 - max(0, 5 - j1)  - max(0, j1  - 250));
    float val = (cAe / (chA * cw0) + cAo / (chA * cw1)
               + cBe / (chB * cw0) + cBo / (chB * cw1)) * (1.0f / (4.0f * 65536.0f));

    // ---- directional term for this thread's 4 pixels (3x3 stencil in tile) --
    {
        float ds = dirterm(sF, sLab, labels, dirs, cvAe, sA, 2*cp + 8, (ciA << 8) + j0)
                 + dirterm(sF, sLab, labels, dirs, cvAo, sA, 2*cp + 9, (ciA << 8) + j1)
                 + dirterm(sF, sLab, labels, dirs, cvBe, sB, 2*cp + 8, (ciB << 8) + j0)
                 + dirterm(sF, sLab, labels, dirs, cvBo, sB, 2*cp + 9, (ciB << 8) + j1);
        val += ds * (1.0f / (16.0f * 65536.0f));
    }

    // ---- block reduce + last-finishing block folds the final sum ----
    __shared__ float wred[4];
    __shared__ bool  slast;
#pragma unroll
    for (int o = 16; o > 0; o >>= 1) val += __shfl_down_sync(0xffffffffu, val, o);
    if ((t & 31) == 0) wred[t >> 5] = val;
    __syncthreads();
    if (t == 0) {
        g_lp[bx] = (wred[0] + wred[1]) + (wred[2] + wred[3]);
        __threadfence();
        unsigned old = atomicAdd(&g_ctr, 1u);
        slast = (old == 511u);
    }
    __syncthreads();

    if (slast) {   // deterministic final reduction over 512 partials
        float v = g_lp[t] + g_lp[t + 128] + g_lp[t + 256] + g_lp[t + 384];
#pragma unroll
        for (int o = 16; o > 0; o >>= 1) v += __shfl_down_sync(0xffffffffu, v, o);
        if ((t & 31) == 0) wred[t >> 5] = v;
        __syncthreads();
        if (t == 0) {
            out[0] = (wred[0] + wred[1]) + (wred[2] + wred[3]);
            g_ctr = 0;   // reset for next graph replay
        }
    }
}

// ---------------------------------------------------------------------------
extern "C" void kernel_launch(void* const* d_in, const int* in_sizes, int n_in,
                              void* d_out, int out_size) {
    const float* feat   = (const float*)d_in[0];
    const int*   labels = (const int*)d_in[1];
    const int*   dirs   = (const int*)d_in[2];
    float* out = (float*)d_out;

    const int smem = 18 * ROWB + 18 * 80 * 4;   // 46080 + 5760 = 51840 B
    cudaFuncSetAttribute(k_local, cudaFuncAttributeMaxDynamicSharedMemorySize, smem);

    k_norm<<<1024, 256>>>(feat);
    k_local<<<512, 128, smem>>>(labels, dirs, out);
}

// round 11
// speedup vs baseline: 1.4628x; 1.0730x over previous
#include <cuda_runtime.h>
#include <cuda_fp16.h>
#include <math.h>

#define NB   4
#define CH   16
#define HWSZ 65536
#define EPSV 1e-6f
#define LOG2E_T 14.4269504089f     // (1/TEMP) * log2(e)
#define LN2F    0.69314718056f

typedef unsigned long long u64;
typedef unsigned int u32;

// Channels-last normalized features in fp16: [n][pix][16 halves] = 8 MB
__device__ u32 g_fnh[(size_t)NB * HWSZ * 8];
__device__ float g_lp[512];
__device__ unsigned int g_ctr = 0;

// ---------------- helpers ----------------
__device__ __forceinline__ u64 f2add(u64 a, u64 b) {
    u64 d; asm("add.rn.f32x2 %0,%1,%2;" : "=l"(d) : "l"(a), "l"(b)); return d;
}
__device__ __forceinline__ u64 pack2(float lo, float hi) {
    u64 d; asm("mov.b64 %0,{%1,%2};" : "=l"(d) : "f"(lo), "f"(hi)); return d;
}
__device__ __forceinline__ void unpack2(u64 v, float& lo, float& hi) {
    asm("mov.b64 {%0,%1},%2;" : "=f"(lo), "=f"(hi) : "l"(v));
}
__device__ __forceinline__ float ex2f(float x) {
    float r; asm("ex2.approx.ftz.f32 %0,%1;" : "=f"(r) : "f"(x)); return r;
}
// fp16 (half2) 16-dim dot: 8 HFMA2 in 2 chains, join, fold, 1 convert
__device__ __forceinline__ float dot16h(const u32 a[8], const u32 b[8]) {
    u32 p, q, r, rs, r2;
    asm("mul.rn.f16x2 %0,%1,%2;" : "=r"(p) : "r"(a[0]), "r"(b[0]));
    asm("mul.rn.f16x2 %0,%1,%2;" : "=r"(q) : "r"(a[1]), "r"(b[1]));
    asm("fma.rn.f16x2 %0,%1,%2,%3;" : "=r"(p) : "r"(a[2]), "r"(b[2]), "r"(p));
    asm("fma.rn.f16x2 %0,%1,%2,%3;" : "=r"(q) : "r"(a[3]), "r"(b[3]), "r"(q));
    asm("fma.rn.f16x2 %0,%1,%2,%3;" : "=r"(p) : "r"(a[4]), "r"(b[4]), "r"(p));
    asm("fma.rn.f16x2 %0,%1,%2,%3;" : "=r"(q) : "r"(a[5]), "r"(b[5]), "r"(q));
    asm("fma.rn.f16x2 %0,%1,%2,%3;" : "=r"(p) : "r"(a[6]), "r"(b[6]), "r"(p));
    asm("fma.rn.f16x2 %0,%1,%2,%3;" : "=r"(q) : "r"(a[7]), "r"(b[7]), "r"(q));
    asm("add.rn.f16x2 %0,%1,%2;" : "=r"(r) : "r"(p), "r"(q));
    asm("prmt.b32 %0,%1,%1,0x1032;" : "=r"(rs) : "r"(r));
    asm("add.rn.f16x2 %0,%1,%2;" : "=r"(r2) : "r"(r), "r"(rs));
    float f;
    asm("{.reg .b16 lo,hi; mov.b32 {lo,hi}, %1; cvt.f32.f16 %0, lo;}"
        : "=f"(f) : "r"(r2));
    return f;
}
// scale 8 half2 regs by splat constant (fp16)
__device__ __forceinline__ void scale16h(u32 h[8], u32 k2) {
#pragma unroll
    for (int i = 0; i < 8; i++)
        asm("mul.rn.f16x2 %0,%1,%2;" : "=r"(h[i]) : "r"(h[i]), "r"(k2));
}
// load 16 halves (as 8 u32) from a parity sub-array with XOR swizzle
__device__ __forceinline__ void load16h(const char* base, int idx, u32 h[8]) {
    int sw = ((idx >> 2) & 1) << 4;
    const char* p = base + (idx << 5);
    uint4 a = *(const uint4*)(p + sw);
    uint4 b = *(const uint4*)(p + (16 ^ sw));
    h[0]=a.x; h[1]=a.y; h[2]=a.z; h[3]=a.w;
    h[4]=b.x; h[5]=b.y; h[6]=b.z; h[7]=b.w;
}

#define ROWB 2560                    // bytes per row slot (40+40 vecs of 32B)
#define HOFF 1280                    // odd-parity sub-array offset

// ---- directional term for ONE center pixel (3x3 stencil inside the tile) ----
__device__ __forceinline__ float dirterm(const char* sF, const int* sLab,
                                         const int* __restrict__ labels,
                                         const int* __restrict__ dirs,
                                         const u32 cv[8], int srow, int xc,
                                         int pix) {
    float dt[NB]; bool mk[NB]; float S = 0.f;
#pragma unroll
    for (int k = 0; k < NB; k++) {
        int dik = dirs[(k * 2 + 0) * HWSZ + pix];
        int djk = dirs[(k * 2 + 1) * HWSZ + pix];
        int sl = srow + dik;
        int x  = xc + djk;
        u32 nv[8]; load16h(sF + sl * ROWB + (x & 1) * HOFF, x >> 1, nv);
        dt[k] = dot16h(cv, nv);              // log2-scaled logit
        int lbn = sLab[sl * 80 + (x & 1) * 40 + (x >> 1)];
        mk[k] = (labels[k * HWSZ + pix] == lbn);
        S += mk[k] ? ex2f(dt[k]) : 0.f;
    }
    float logS = __logf(S + EPSV);
    float s = 0.f;
#pragma unroll
    for (int k = 0; k < NB; k++)
        s += mk[k] ? (logS - LN2F * dt[k]) : __int_as_float(0x7f800000);
    return s;
}

// ---------------------------------------------------------------------------
// Kernel 1: L2-normalize + transpose + fp16 quantize. 1 pixel/thread.
// ---------------------------------------------------------------------------
__global__ void __launch_bounds__(256)
k_norm(const float* __restrict__ f) {
    int idx = blockIdx.x * 256 + threadIdx.x;  // 0 .. N*HW-1
    int n   = idx >> 16;
    int pix = idx & 65535;
    const float* b = f + (size_t)n * CH * HWSZ + pix;
    float v[CH];
    float ss = 0.f;
#pragma unroll
    for (int c = 0; c < CH; c++) {
        v[c] = b[(size_t)c * HWSZ];
        ss = fmaf(v[c], v[c], ss);
    }
    float inv = 1.0f / fmaxf(sqrtf(ss), 1e-12f);
    u32 h[8];
#pragma unroll
    for (int c2 = 0; c2 < 8; c2++) {
        __half2 hh = __floats2half2_rn(v[c2*2] * inv, v[c2*2+1] * inv);
        h[c2] = *(u32*)&hh;
    }
    uint4* o = (uint4*)(g_fnh + (size_t)idx * 8);
    o[0] = make_uint4(h[0], h[1], h[2], h[3]);
    o[1] = make_uint4(h[4], h[5], h[6], h[7]);
}

// ---------------------------------------------------------------------------
// Kernel 2: local 11x11 + directional, fused per-pixel.
// Block = (n, 8 center rows, 64-col quarter). 128 threads, 2x2 quad each.
// Out-of-image exclusion via label sentinel only (no vld predicates);
// v=0 / v=11 peeled so the main loop has no row-ok masks and no dead dots.
// ---------------------------------------------------------------------------
__global__ void __launch_bounds__(128, 4)
k_local(const int* __restrict__ labels, const int* __restrict__ dirs,
        float* __restrict__ out) {
    extern __shared__ char sm[];
    char* sF   = sm;                      // 18 * 2560 = 46080 B
    int*  sLab = (int*)(sm + 18 * ROWB);  // 18 * 80 ints = 5760 B

    const int bx  = blockIdx.x;           // 0..511
    const int n   = bx >> 7;
    const int rem = bx & 127;
    const int i0  = (rem >> 2) << 3;      // first center row (mult of 8)
    const int hq  = rem & 3;              // which 64-col quarter
    const int cb  = hq * 64 - 8;          // tile base col (global)
    const int t   = threadIdx.x;

    // ---- fill halo: 18 rows x 80 cols (OOB labels -> sentinel) ----
    {
        const uint4* src = (const uint4*)(g_fnh + (size_t)n * HWSZ * 8);
#pragma unroll
        for (int k = 0; k < 23; k++) {
            int lin = t + (k << 7);           // need 2880
            if (lin < 2880) {
                int rr = lin / 160;
                int w  = lin - rr * 160;
                int ch = w & 1;
                int x  = w >> 1;              // tile col 0..79
                int row = i0 - 5 + rr;
                int g   = cb + x;
                if ((unsigned)row < 256u && (unsigned)g < 256u) {
                    uint4 v = src[(size_t)((row << 8) + g) * 2 + ch];
                    int parity = x & 1, e = x >> 1;
                    *(uint4*)(sF + rr * ROWB + parity * HOFF + (e << 5)
                              + ((ch ^ ((e >> 2) & 1)) << 4)) = v;
                }
            }
        }
        const int* ls = labels + n * HWSZ;
#pragma unroll
        for (int k = 0; k < 12; k++) {
            int lin = t + (k << 7);           // need 1440
            if (lin < 1440) {
                int rr = lin / 80;
                int x  = lin - rr * 80;
                int row = i0 - 5 + rr;
                int g   = cb + x;
                bool ok = ((unsigned)row < 256u) && ((unsigned)g < 256u);
                sLab[rr * 80 + (x & 1) * 40 + (x >> 1)] =
                    ok ? ls[(row << 8) + g] : (int)0x80000000;
            }
        }
    }
    __syncthreads();

    const int rp = t >> 5;               // 0..3 (warp-uniform)
    const int cp = t & 31;
    const int tc = cp + 4;
    const int sA = 2 * rp + 5;
    const int sB = sA + 1;

    u32 cvAe[8], cvAo[8], cvBe[8], cvBo[8];
    load16h(sF + sA * ROWB,        tc, cvAe);
    load16h(sF + sA * ROWB + HOFF, tc, cvAo);
    load16h(sF + sB * ROWB,        tc, cvBe);
    load16h(sF + sB * ROWB + HOFF, tc, cvBo);
    __half2 kt = __floats2half2_rn(LOG2E_T, LOG2E_T);
    u32 kt2 = *(u32*)&kt;
    scale16h(cvAe, kt2); scale16h(cvAo, kt2);
    scale16h(cvBe, kt2); scale16h(cvBo, kt2);
    const int clAe = sLab[sA * 80 + tc];
    const int clAo = sLab[sA * 80 + 40 + tc];
    const int clBe = sLab[sB * 80 + tc];
    const int clBo = sLab[sB * 80 + 40 + tc];

    u64 SDAe = 0, SDAo = 0, SDBe = 0, SDBo = 0;   // packed {S, D}
    int MAe = 0, MAo = 0, MBe = 0, MBo = 0;

    // ================= v = 0 peel: A-centers only =================
    {
        int s   = 2 * rp;                  // slot 0..6
        int row = i0 - 5 + s;
        if (row >= 0) {                    // warp-uniform
            const char* rowE = sF + s * ROWB;
            const char* rowO = rowE + HOFF;
            const int* labE = sLab + s * 80;
            const int* labO = labE + 40;
#pragma unroll
            for (int u = 0; u < 6; u++) {
                int e = cp + 2 + u;
                u32 nv[8]; load16h(rowE, e, nv);
                int lb = labE[e];
                float dAo = dot16h(cvAo, nv);
                float eAo = ex2f(dAo);
                if (lb == clAo) { SDAo = f2add(SDAo, pack2(eAo, dAo)); MAo++; }
                if (u != 5) {
                    float dAe = dot16h(cvAe, nv);
                    float eAe = ex2f(dAe);
                    if (lb == clAe) { SDAe = f2add(SDAe, pack2(eAe, dAe)); MAe++; }
                }
            }
#pragma unroll
            for (int u = 0; u < 6; u++) {
                int o = cp + 1 + u;
                u32 nv[8]; load16h(rowO, o, nv);
                int lb = labO[o];
                float dAe = dot16h(cvAe, nv);
                float eAe = ex2f(dAe);
                if (lb == clAe) { SDAe = f2add(SDAe, pack2(eAe, dAe)); MAe++; }
                if (u != 0) {
                    float dAo = dot16h(cvAo, nv);
                    float eAo = ex2f(dAo);
                    if (lb == clAo) { SDAo = f2add(SDAo, pack2(eAo, dAo)); MAo++; }
                }
            }
        }
    }

    // ================= main loop v = 1..10: all four centers =================
#pragma unroll 1
    for (int v = 1; v <= 10; v++) {
        int s   = 2 * rp + v;
        int row = i0 - 5 + s;
        if ((unsigned)row >= 256u) continue;   // warp-uniform
        const char* rowE = sF + s * ROWB;
        const char* rowO = rowE + HOFF;
        const int* labE = sLab + s * 80;
        const int* labO = labE + 40;

        // even-pixel neighbors
#pragma unroll
        for (int u = 0; u < 6; u++) {
            int e = cp + 2 + u;
            u32 nv[8]; load16h(rowE, e, nv);
            int lb = labE[e];
            {
                float dAo = dot16h(cvAo, nv);
                float dBo = dot16h(cvBo, nv);
                float eAo = ex2f(dAo), eBo = ex2f(dBo);
                if (lb == clAo) { SDAo = f2add(SDAo, pack2(eAo, dAo)); MAo++; }
                if (lb == clBo) { SDBo = f2add(SDBo, pack2(eBo, dBo)); MBo++; }
            }
            if (u != 5) {
                float dAe = dot16h(cvAe, nv);
                float dBe = dot16h(cvBe, nv);
                float eAe = ex2f(dAe), eBe = ex2f(dBe);
                if (lb == clAe) { SDAe = f2add(SDAe, pack2(eAe, dAe)); MAe++; }
                if (lb == clBe) { SDBe = f2add(SDBe, pack2(eBe, dBe)); MBe++; }
            }
        }
        // odd-pixel neighbors
#pragma unroll
        for (int u = 0; u < 6; u++) {
            int o = cp + 1 + u;
            u32 nv[8]; load16h(rowO, o, nv);
            int lb = labO[o];
            {
                float dAe = dot16h(cvAe, nv);
                float dBe = dot16h(cvBe, nv);
                float eAe = ex2f(dAe), eBe = ex2f(dBe);
                if (lb == clAe) { SDAe = f2add(SDAe, pack2(eAe, dAe)); MAe++; }
                if (lb == clBe) { SDBe = f2add(SDBe, pack2(eBe, dBe)); MBe++; }
            }
            if (u != 0) {
                float dAo = dot16h(cvAo, nv);
                float dBo = dot16h(cvBo, nv);
                float eAo = ex2f(dAo), eBo = ex2f(dBo);
                if (lb == clAo) { SDAo = f2add(SDAo, pack2(eAo, dAo)); MAo++; }
                if (lb == clBo) { SDBo = f2add(SDBo, pack2(eBo, dBo)); MBo++; }
            }
        }
    }

    // ================= v = 11 peel: B-centers only =================
    {
        int s   = 2 * rp + 11;             // slot 11..17
        int row = i0 - 5 + s;
        if (row < 256) {                   // warp-uniform
            const char* rowE = sF + s * ROWB;
            const char* rowO = rowE + HOFF;
            const int* labE = sLab + s * 80;
            const int* labO = labE + 40;
#pragma unroll
            for (int u = 0; u < 6; u++) {
                int e = cp + 2 + u;
                u32 nv[8]; load16h(rowE, e, nv);
                int lb = labE[e];
                float dBo = dot16h(cvBo, nv);
                float eBo = ex2f(dBo);
                if (lb == clBo) { SDBo = f2add(SDBo, pack2(eBo, dBo)); MBo++; }
                if (u != 5) {
                    float dBe = dot16h(cvBe, nv);
                    float eBe = ex2f(dBe);
                    if (lb == clBe) { SDBe = f2add(SDBe, pack2(eBe, dBe)); MBe++; }
                }
            }
#pragma unroll
            for (int u = 0; u < 6; u++) {
                int o = cp + 1 + u;
                u32 nv[8]; load16h(rowO, o, nv);
                int lb = labO[o];
                float dBe = dot16h(cvBe, nv);
                float eBe = ex2f(dBe);
                if (lb == clBe) { SDBe = f2add(SDBe, pack2(eBe, dBe)); MBe++; }
                if (u != 0) {
                    float dBo = dot16h(cvBo, nv);
                    float eBo = ex2f(dBo);
                    if (lb == clBo) { SDBo = f2add(SDBo, pack2(eBo, dBo)); MBo++; }
                }
            }
        }
    }

    float SAe, DAe, SAo, DAo, SBe, DBe, SBo, DBo;
    unpack2(SDAe, SAe, DAe);  unpack2(SDAo, SAo, DAo);
    unpack2(SDBe, SBe, DBe);  unpack2(SDBo, SBo, DBo);

    float cAe = fmaf((float)MAe, __logf(SAe + EPSV), -LN2F * DAe);
    float cAo = fmaf((float)MAo, __logf(SAo + EPSV), -LN2F * DAo);
    float cBe = fmaf((float)MBe, __logf(SBe + EPSV), -LN2F * DBe);
    float cBo = fmaf((float)MBo, __logf(SBo + EPSV), -LN2F * DBo);
    int ciA = i0 + 2 * rp, ciB = ciA + 1;
    int j0  = hq * 64 + 2 * cp, j1 = j0 + 1;
    float chA = (float)(11 - max(0, 5 - ciA) - max(0, ciA - 250));
    float chB = (float)(11 - max(0, 5 - ciB) - max(0, ciB - 250));
    float cw0 = (float)(11 - max(0, 5 - j0)  - max(0, j0  - 250));
    float cw1 = (float)(11 - max(0, 5 - j1)  - max(0, j1  - 250));
    float val = (cAe / (chA * cw0) + cAo / (chA * cw1)
               + cBe / (chB * cw0) + cBo / (chB * cw1)) * (1.0f / (4.0f * 65536.0f));

    // ---- directional term for this thread's 4 pixels (3x3 stencil in tile) --
    {
        float ds = dirterm(sF, sLab, labels, dirs, cvAe, sA, 2*cp + 8, (ciA << 8) + j0)
                 + dirterm(sF, sLab, labels, dirs, cvAo, sA, 2*cp + 9, (ciA << 8) + j1)
                 + dirterm(sF, sLab, labels, dirs, cvBe, sB, 2*cp + 8, (ciB << 8) + j0)
                 + dirterm(sF, sLab, labels, dirs, cvBo, sB, 2*cp + 9, (ciB << 8) + j1);
        val += ds * (1.0f / (16.0f * 65536.0f));
    }

    // ---- block reduce + last-finishing block folds the final sum ----
    __shared__ float wred[4];
    __shared__ bool  slast;
#pragma unroll
    for (int o = 16; o > 0; o >>= 1) val += __shfl_down_sync(0xffffffffu, val, o);
    if ((t & 31) == 0) wred[t >> 5] = val;
    __syncthreads();
    if (t == 0) {
        g_lp[bx] = (wred[0] + wred[1]) + (wred[2] + wred[3]);
        __threadfence();
        unsigned old = atomicAdd(&g_ctr, 1u);
        slast = (old == 511u);
    }
    __syncthreads();

    if (slast) {   // deterministic final reduction over 512 partials
        float v = g_lp[t] + g_lp[t + 128] + g_lp[t + 256] + g_lp[t + 384];
#pragma unroll
        for (int o = 16; o > 0; o >>= 1) v += __shfl_down_sync(0xffffffffu, v, o);
        if ((t & 31) == 0) wred[t >> 5] = v;
        __syncthreads();
        if (t == 0) {
            out[0] = (wred[0] + wred[1]) + (wred[2] + wred[3]);
            g_ctr = 0;   // reset for next graph replay
        }
    }
}

// ---------------------------------------------------------------------------
extern "C" void kernel_launch(void* const* d_in, const int* in_sizes, int n_in,
                              void* d_out, int out_size) {
    const float* feat   = (const float*)d_in[0];
    const int*   labels = (const int*)d_in[1];
    const int*   dirs   = (const int*)d_in[2];
    float* out = (float*)d_out;

    const int smem = 18 * ROWB + 18 * 80 * 4;   // 46080 + 5760 = 51840 B
    cudaFuncSetAttribute(k_local, cudaFuncAttributeMaxDynamicSharedMemorySize, smem);

    k_norm<<<1024, 256>>>(feat);
    k_local<<<512, 128, smem>>>(labels, dirs, out);
}

// round 12
// speedup vs baseline: 1.5337x; 1.0485x over previous
#include <cuda_runtime.h>
#include <cuda_fp16.h>
#include <math.h>

#define NB   4
#define CH   16
#define HWSZ 65536
#define EPSV 1e-6f
#define LOG2E_T 14.4269504089f     // (1/TEMP) * log2(e)
#define LN2F    0.69314718056f

typedef unsigned long long u64;
typedef unsigned int u32;

__device__ float g_lp[512];
__device__ unsigned int g_ctr = 0;

// ---------------- helpers ----------------
__device__ __forceinline__ u64 f2add(u64 a, u64 b) {
    u64 d; asm("add.rn.f32x2 %0,%1,%2;" : "=l"(d) : "l"(a), "l"(b)); return d;
}
__device__ __forceinline__ u64 pack2(float lo, float hi) {
    u64 d; asm("mov.b64 %0,{%1,%2};" : "=l"(d) : "f"(lo), "f"(hi)); return d;
}
__device__ __forceinline__ void unpack2(u64 v, float& lo, float& hi) {
    asm("mov.b64 {%0,%1},%2;" : "=f"(lo), "=f"(hi) : "l"(v));
}
__device__ __forceinline__ float ex2f(float x) {
    float r; asm("ex2.approx.ftz.f32 %0,%1;" : "=f"(r) : "f"(x)); return r;
}
// fp16 (half2) 16-dim dot: 8 HFMA2 in 2 chains, join, fold, 1 convert
__device__ __forceinline__ float dot16h(const u32 a[8], const u32 b[8]) {
    u32 p, q, r, rs, r2;
    asm("mul.rn.f16x2 %0,%1,%2;" : "=r"(p) : "r"(a[0]), "r"(b[0]));
    asm("mul.rn.f16x2 %0,%1,%2;" : "=r"(q) : "r"(a[1]), "r"(b[1]));
    asm("fma.rn.f16x2 %0,%1,%2,%3;" : "=r"(p) : "r"(a[2]), "r"(b[2]), "r"(p));
    asm("fma.rn.f16x2 %0,%1,%2,%3;" : "=r"(q) : "r"(a[3]), "r"(b[3]), "r"(q));
    asm("fma.rn.f16x2 %0,%1,%2,%3;" : "=r"(p) : "r"(a[4]), "r"(b[4]), "r"(p));
    asm("fma.rn.f16x2 %0,%1,%2,%3;" : "=r"(q) : "r"(a[5]), "r"(b[5]), "r"(q));
    asm("fma.rn.f16x2 %0,%1,%2,%3;" : "=r"(p) : "r"(a[6]), "r"(b[6]), "r"(p));
    asm("fma.rn.f16x2 %0,%1,%2,%3;" : "=r"(q) : "r"(a[7]), "r"(b[7]), "r"(q));
    asm("add.rn.f16x2 %0,%1,%2;" : "=r"(r) : "r"(p), "r"(q));
    asm("prmt.b32 %0,%1,%1,0x1032;" : "=r"(rs) : "r"(r));
    asm("add.rn.f16x2 %0,%1,%2;" : "=r"(r2) : "r"(r), "r"(rs));
    float f;
    asm("{.reg .b16 lo,hi; mov.b32 {lo,hi}, %1; cvt.f32.f16 %0, lo;}"
        : "=f"(f) : "r"(r2));
    return f;
}
// scale 8 half2 regs by splat constant (fp16)
__device__ __forceinline__ void scale16h(u32 h[8], u32 k2) {
#pragma unroll
    for (int i = 0; i < 8; i++)
        asm("mul.rn.f16x2 %0,%1,%2;" : "=r"(h[i]) : "r"(h[i]), "r"(k2));
}
// load 16 halves (as 8 u32) from a parity sub-array with XOR swizzle
__device__ __forceinline__ void load16h(const char* base, int idx, u32 h[8]) {
    int sw = ((idx >> 2) & 1) << 4;
    const char* p = base + (idx << 5);
    uint4 a = *(const uint4*)(p + sw);
    uint4 b = *(const uint4*)(p + (16 ^ sw));
    h[0]=a.x; h[1]=a.y; h[2]=a.z; h[3]=a.w;
    h[4]=b.x; h[5]=b.y; h[6]=b.z; h[7]=b.w;
}

#define ROWB 2560                    // bytes per row slot (40+40 vecs of 32B)
#define HOFF 1280                    // odd-parity sub-array offset

// ---- directional term for ONE center pixel (3x3 stencil inside the tile) ----
__device__ __forceinline__ float dirterm(const char* sF, const int* sLab,
                                         const int* __restrict__ labels,
                                         const int* __restrict__ dirs,
                                         const u32 cv[8], int srow, int xc,
                                         int pix) {
    float dt[NB]; bool mk[NB]; float S = 0.f;
#pragma unroll
    for (int k = 0; k < NB; k++) {
        int dik = dirs[(k * 2 + 0) * HWSZ + pix];
        int djk = dirs[(k * 2 + 1) * HWSZ + pix];
        int sl = srow + dik;
        int x  = xc + djk;
        u32 nv[8]; load16h(sF + sl * ROWB + (x & 1) * HOFF, x >> 1, nv);
        dt[k] = dot16h(cv, nv);              // log2-scaled logit
        int lbn = sLab[sl * 80 + (x & 1) * 40 + (x >> 1)];
        mk[k] = (labels[k * HWSZ + pix] == lbn);
        S += mk[k] ? ex2f(dt[k]) : 0.f;
    }
    float logS = __logf(S + EPSV);
    float s = 0.f;
#pragma unroll
    for (int k = 0; k < NB; k++)
        s += mk[k] ? (logS - LN2F * dt[k]) : __int_as_float(0x7f800000);
    return s;
}

// ---------------------------------------------------------------------------
// Single fused kernel: halo fill normalizes raw fp32 features in-register
// (identical math to the old k_norm), then local 11x11 + directional terms.
// Block = (n, 8 center rows, 64-col quarter). 128 threads, 2x2 quad each.
// ---------------------------------------------------------------------------
__global__ void __launch_bounds__(128, 4)
k_local(const float* __restrict__ feat, const int* __restrict__ labels,
        const int* __restrict__ dirs, float* __restrict__ out) {
    extern __shared__ char sm[];
    char* sF   = sm;                      // 18 * 2560 = 46080 B
    int*  sLab = (int*)(sm + 18 * ROWB);  // 18 * 80 ints = 5760 B

    const int bx  = blockIdx.x;           // 0..511
    const int n   = bx >> 7;
    const int rem = bx & 127;
    const int i0  = (rem >> 2) << 3;      // first center row (mult of 8)
    const int hq  = rem & 3;              // which 64-col quarter
    const int cb  = hq * 64 - 8;          // tile base col (global)
    const int t   = threadIdx.x;

    // ---- fill halo: 18 rows x 80 cols; normalize+quantize inline ----
    {
        const float* fbase = feat + (size_t)n * CH * HWSZ;
#pragma unroll 1
        for (int k = 0; k < 12; k++) {
            int lin = t + (k << 7);           // need 1440
            if (lin < 1440) {
                int rr = lin / 80;
                int x  = lin - rr * 80;
                int row = i0 - 5 + rr;
                int g   = cb + x;
                if ((unsigned)row < 256u && (unsigned)g < 256u) {
                    const float* p = fbase + (row << 8) + g;
                    float v[CH]; float ss = 0.f;
#pragma unroll
                    for (int c = 0; c < CH; c++) {
                        v[c] = p[(size_t)c * HWSZ];
                        ss = fmaf(v[c], v[c], ss);
                    }
                    float inv = 1.0f / fmaxf(sqrtf(ss), 1e-12f);
                    u32 h[8];
#pragma unroll
                    for (int c2 = 0; c2 < 8; c2++) {
                        __half2 hh = __floats2half2_rn(v[c2*2] * inv,
                                                       v[c2*2+1] * inv);
                        h[c2] = *(u32*)&hh;
                    }
                    int e = x >> 1;
                    char* dst = sF + rr * ROWB + (x & 1) * HOFF + (e << 5);
                    int swz = ((e >> 2) & 1) << 4;
                    *(uint4*)(dst + swz)        = make_uint4(h[0], h[1], h[2], h[3]);
                    *(uint4*)(dst + (16 ^ swz)) = make_uint4(h[4], h[5], h[6], h[7]);
                }
            }
        }
        const int* ls = labels + n * HWSZ;
#pragma unroll
        for (int k = 0; k < 12; k++) {
            int lin = t + (k << 7);           // need 1440
            if (lin < 1440) {
                int rr = lin / 80;
                int x  = lin - rr * 80;
                int row = i0 - 5 + rr;
                int g   = cb + x;
                bool ok = ((unsigned)row < 256u) && ((unsigned)g < 256u);
                sLab[rr * 80 + (x & 1) * 40 + (x >> 1)] =
                    ok ? ls[(row << 8) + g] : (int)0x80000000;
            }
        }
    }
    __syncthreads();

    const int rp = t >> 5;               // 0..3 (warp-uniform)
    const int cp = t & 31;
    const int tc = cp + 4;
    const int sA = 2 * rp + 5;
    const int sB = sA + 1;

    u32 cvAe[8], cvAo[8], cvBe[8], cvBo[8];
    load16h(sF + sA * ROWB,        tc, cvAe);
    load16h(sF + sA * ROWB + HOFF, tc, cvAo);
    load16h(sF + sB * ROWB,        tc, cvBe);
    load16h(sF + sB * ROWB + HOFF, tc, cvBo);
    __half2 kt = __floats2half2_rn(LOG2E_T, LOG2E_T);
    u32 kt2 = *(u32*)&kt;
    scale16h(cvAe, kt2); scale16h(cvAo, kt2);
    scale16h(cvBe, kt2); scale16h(cvBo, kt2);
    const int clAe = sLab[sA * 80 + tc];
    const int clAo = sLab[sA * 80 + 40 + tc];
    const int clBe = sLab[sB * 80 + tc];
    const int clBo = sLab[sB * 80 + 40 + tc];

    u64 SDAe = 0, SDAo = 0, SDBe = 0, SDBo = 0;   // packed {S, D}
    int MAe = 0, MAo = 0, MBe = 0, MBo = 0;

    // ================= v = 0 peel: A-centers only =================
    {
        int s   = 2 * rp;                  // slot 0..6
        int row = i0 - 5 + s;
        if (row >= 0) {                    // warp-uniform
            const char* rowE = sF + s * ROWB;
            const char* rowO = rowE + HOFF;
            const int* labE = sLab + s * 80;
            const int* labO = labE + 40;
#pragma unroll
            for (int u = 0; u < 6; u++) {
                int e = cp + 2 + u;
                u32 nv[8]; load16h(rowE, e, nv);
                int lb = labE[e];
                float dAo = dot16h(cvAo, nv);
                float eAo = ex2f(dAo);
                if (lb == clAo) { SDAo = f2add(SDAo, pack2(eAo, dAo)); MAo++; }
                if (u != 5) {
                    float dAe = dot16h(cvAe, nv);
                    float eAe = ex2f(dAe);
                    if (lb == clAe) { SDAe = f2add(SDAe, pack2(eAe, dAe)); MAe++; }
                }
            }
#pragma unroll
            for (int u = 0; u < 6; u++) {
                int o = cp + 1 + u;
                u32 nv[8]; load16h(rowO, o, nv);
                int lb = labO[o];
                float dAe = dot16h(cvAe, nv);
                float eAe = ex2f(dAe);
                if (lb == clAe) { SDAe = f2add(SDAe, pack2(eAe, dAe)); MAe++; }
                if (u != 0) {
                    float dAo = dot16h(cvAo, nv);
                    float eAo = ex2f(dAo);
                    if (lb == clAo) { SDAo = f2add(SDAo, pack2(eAo, dAo)); MAo++; }
                }
            }
        }
    }

    // ================= main loop v = 1..10: all four centers =================
#pragma unroll 1
    for (int v = 1; v <= 10; v++) {
        int s   = 2 * rp + v;
        int row = i0 - 5 + s;
        if ((unsigned)row >= 256u) continue;   // warp-uniform
        const char* rowE = sF + s * ROWB;
        const char* rowO = rowE + HOFF;
        const int* labE = sLab + s * 80;
        const int* labO = labE + 40;

        // even-pixel neighbors
#pragma unroll
        for (int u = 0; u < 6; u++) {
            int e = cp + 2 + u;
            u32 nv[8]; load16h(rowE, e, nv);
            int lb = labE[e];
            {
                float dAo = dot16h(cvAo, nv);
                float dBo = dot16h(cvBo, nv);
                float eAo = ex2f(dAo), eBo = ex2f(dBo);
                if (lb == clAo) { SDAo = f2add(SDAo, pack2(eAo, dAo)); MAo++; }
                if (lb == clBo) { SDBo = f2add(SDBo, pack2(eBo, dBo)); MBo++; }
            }
            if (u != 5) {
                float dAe = dot16h(cvAe, nv);
                float dBe = dot16h(cvBe, nv);
                float eAe = ex2f(dAe), eBe = ex2f(dBe);
                if (lb == clAe) { SDAe = f2add(SDAe, pack2(eAe, dAe)); MAe++; }
                if (lb == clBe) { SDBe = f2add(SDBe, pack2(eBe, dBe)); MBe++; }
            }
        }
        // odd-pixel neighbors
#pragma unroll
        for (int u = 0; u < 6; u++) {
            int o = cp + 1 + u;
            u32 nv[8]; load16h(rowO, o, nv);
            int lb = labO[o];
            {
                float dAe = dot16h(cvAe, nv);
                float dBe = dot16h(cvBe, nv);
                float eAe = ex2f(dAe), eBe = ex2f(dBe);
                if (lb == clAe) { SDAe = f2add(SDAe, pack2(eAe, dAe)); MAe++; }
                if (lb == clBe) { SDBe = f2add(SDBe, pack2(eBe, dBe)); MBe++; }
            }
            if (u != 0) {
                float dAo = dot16h(cvAo, nv);
                float dBo = dot16h(cvBo, nv);
                float eAo = ex2f(dAo), eBo = ex2f(dBo);
                if (lb == clAo) { SDAo = f2add(SDAo, pack2(eAo, dAo)); MAo++; }
                if (lb == clBo) { SDBo = f2add(SDBo, pack2(eBo, dBo)); MBo++; }
            }
        }
    }

    // ================= v = 11 peel: B-centers only =================
    {
        int s   = 2 * rp + 11;             // slot 11..17
        int row = i0 - 5 + s;
        if (row < 256) {                   // warp-uniform
            const char* rowE = sF + s * ROWB;
            const char* rowO = rowE + HOFF;
            const int* labE = sLab + s * 80;
            const int* labO = labE + 40;
#pragma unroll
            for (int u = 0; u < 6; u++) {
                int e = cp + 2 + u;
                u32 nv[8]; load16h(rowE, e, nv);
                int lb = labE[e];
                float dBo = dot16h(cvBo, nv);
                float eBo = ex2f(dBo);
                if (lb == clBo) { SDBo = f2add(SDBo, pack2(eBo, dBo)); MBo++; }
                if (u != 5) {
                    float dBe = dot16h(cvBe, nv);
                    float eBe = ex2f(dBe);
                    if (lb == clBe) { SDBe = f2add(SDBe, pack2(eBe, dBe)); MBe++; }
                }
            }
#pragma unroll
            for (int u = 0; u < 6; u++) {
                int o = cp + 1 + u;
                u32 nv[8]; load16h(rowO, o, nv);
                int lb = labO[o];
                float dBe = dot16h(cvBe, nv);
                float eBe = ex2f(dBe);
                if (lb == clBe) { SDBe = f2add(SDBe, pack2(eBe, dBe)); MBe++; }
                if (u != 0) {
                    float dBo = dot16h(cvBo, nv);
                    float eBo = ex2f(dBo);
                    if (lb == clBo) { SDBo = f2add(SDBo, pack2(eBo, dBo)); MBo++; }
                }
            }
        }
    }

    float SAe, DAe, SAo, DAo, SBe, DBe, SBo, DBo;
    unpack2(SDAe, SAe, DAe);  unpack2(SDAo, SAo, DAo);
    unpack2(SDBe, SBe, DBe);  unpack2(SDBo, SBo, DBo);

    float cAe = fmaf((float)MAe, __logf(SAe + EPSV), -LN2F * DAe);
    float cAo = fmaf((float)MAo, __logf(SAo + EPSV), -LN2F * DAo);
    float cBe = fmaf((float)MBe, __logf(SBe + EPSV), -LN2F * DBe);
    float cBo = fmaf((float)MBo, __logf(SBo + EPSV), -LN2F * DBo);
    int ciA = i0 + 2 * rp, ciB = ciA + 1;
    int j0  = hq * 64 + 2 * cp, j1 = j0 + 1;
    float chA = (float)(11 - max(0, 5 - ciA) - max(0, ciA - 250));
    float chB = (float)(11 - max(0, 5 - ciB) - max(0, ciB - 250));
    float cw0 = (float)(11 - max(0, 5 - j0)  - max(0, j0  - 250));
    float cw1 = (float)(11 - max(0, 5 - j1)  - max(0, j1  - 250));
    float val = (cAe / (chA * cw0) + cAo / (chA * cw1)
               + cBe / (chB * cw0) + cBo / (chB * cw1)) * (1.0f / (4.0f * 65536.0f));

    // ---- directional term for this thread's 4 pixels (3x3 stencil in tile) --
    {
        float ds = dirterm(sF, sLab, labels, dirs, cvAe, sA, 2*cp + 8, (ciA << 8) + j0)
                 + dirterm(sF, sLab, labels, dirs, cvAo, sA, 2*cp + 9, (ciA << 8) + j1)
                 + dirterm(sF, sLab, labels, dirs, cvBe, sB, 2*cp + 8, (ciB << 8) + j0)
                 + dirterm(sF, sLab, labels, dirs, cvBo, sB, 2*cp + 9, (ciB << 8) + j1);
        val += ds * (1.0f / (16.0f * 65536.0f));
    }

    // ---- block reduce + last-finishing block folds the final sum ----
    __shared__ float wred[4];
    __shared__ bool  slast;
#pragma unroll
    for (int o = 16; o > 0; o >>= 1) val += __shfl_down_sync(0xffffffffu, val, o);
    if ((t & 31) == 0) wred[t >> 5] = val;
    __syncthreads();
    if (t == 0) {
        g_lp[bx] = (wred[0] + wred[1]) + (wred[2] + wred[3]);
        __threadfence();
        unsigned old = atomicAdd(&g_ctr, 1u);
        slast = (old == 511u);
    }
    __syncthreads();

    if (slast) {   // deterministic final reduction over 512 partials
        float v = g_lp[t] + g_lp[t + 128] + g_lp[t + 256] + g_lp[t + 384];
#pragma unroll
        for (int o = 16; o > 0; o >>= 1) v += __shfl_down_sync(0xffffffffu, v, o);
        if ((t & 31) == 0) wred[t >> 5] = v;
        __syncthreads();
        if (t == 0) {
            out[0] = (wred[0] + wred[1]) + (wred[2] + wred[3]);
            g_ctr = 0;   // reset for next graph replay
        }
    }
}

// ---------------------------------------------------------------------------
extern "C" void kernel_launch(void* const* d_in, const int* in_sizes, int n_in,
                              void* d_out, int out_size) {
    const float* feat   = (const float*)d_in[0];
    const int*   labels = (const int*)d_in[1];
    const int*   dirs   = (const int*)d_in[2];
    float* out = (float*)d_out;

    const int smem = 18 * ROWB + 18 * 80 * 4;   // 46080 + 5760 = 51840 B
    cudaFuncSetAttribute(k_local, cudaFuncAttributeMaxDynamicSharedMemorySize, smem);

    k_local<<<512, 128, smem>>>(feat, labels, dirs, out);
}

// round 13
// speedup vs baseline: 1.5489x; 1.0099x over previous
#include <cuda_runtime.h>
#include <cuda_fp16.h>
#include <math.h>

#define NB   4
#define CH   16
#define HWSZ 65536
#define EPSV 1e-6f
#define LOG2E_T 14.4269504089f     // (1/TEMP) * log2(e)
#define LN2F    0.69314718056f

typedef unsigned long long u64;
typedef unsigned int u32;

__device__ float g_lp[512];
__device__ unsigned int g_ctr = 0;

// ---------------- helpers ----------------
__device__ __forceinline__ u64 f2add(u64 a, u64 b) {
    u64 d; asm("add.rn.f32x2 %0,%1,%2;" : "=l"(d) : "l"(a), "l"(b)); return d;
}
__device__ __forceinline__ u64 pack2(float lo, float hi) {
    u64 d; asm("mov.b64 %0,{%1,%2};" : "=l"(d) : "f"(lo), "f"(hi)); return d;
}
__device__ __forceinline__ void unpack2(u64 v, float& lo, float& hi) {
    asm("mov.b64 {%0,%1},%2;" : "=f"(lo), "=f"(hi) : "l"(v));
}
__device__ __forceinline__ float ex2f(float x) {
    float r; asm("ex2.approx.ftz.f32 %0,%1;" : "=f"(r) : "f"(x)); return r;
}
// fp16 (half2) 16-dim dot: 8 HFMA2 in 2 chains, join, fold, 1 convert
__device__ __forceinline__ float dot16h(const u32 a[8], const u32 b[8]) {
    u32 p, q, r, rs, r2;
    asm("mul.rn.f16x2 %0,%1,%2;" : "=r"(p) : "r"(a[0]), "r"(b[0]));
    asm("mul.rn.f16x2 %0,%1,%2;" : "=r"(q) : "r"(a[1]), "r"(b[1]));
    asm("fma.rn.f16x2 %0,%1,%2,%3;" : "=r"(p) : "r"(a[2]), "r"(b[2]), "r"(p));
    asm("fma.rn.f16x2 %0,%1,%2,%3;" : "=r"(q) : "r"(a[3]), "r"(b[3]), "r"(q));
    asm("fma.rn.f16x2 %0,%1,%2,%3;" : "=r"(p) : "r"(a[4]), "r"(b[4]), "r"(p));
    asm("fma.rn.f16x2 %0,%1,%2,%3;" : "=r"(q) : "r"(a[5]), "r"(b[5]), "r"(q));
    asm("fma.rn.f16x2 %0,%1,%2,%3;" : "=r"(p) : "r"(a[6]), "r"(b[6]), "r"(p));
    asm("fma.rn.f16x2 %0,%1,%2,%3;" : "=r"(q) : "r"(a[7]), "r"(b[7]), "r"(q));
    asm("add.rn.f16x2 %0,%1,%2;" : "=r"(r) : "r"(p), "r"(q));
    asm("prmt.b32 %0,%1,%1,0x1032;" : "=r"(rs) : "r"(r));
    asm("add.rn.f16x2 %0,%1,%2;" : "=r"(r2) : "r"(r), "r"(rs));
    float f;
    asm("{.reg .b16 lo,hi; mov.b32 {lo,hi}, %1; cvt.f32.f16 %0, lo;}"
        : "=f"(f) : "r"(r2));
    return f;
}
// scale 8 half2 regs by splat constant (fp16)
__device__ __forceinline__ void scale16h(u32 h[8], u32 k2) {
#pragma unroll
    for (int i = 0; i < 8; i++)
        asm("mul.rn.f16x2 %0,%1,%2;" : "=r"(h[i]) : "r"(h[i]), "r"(k2));
}

// Chunk-split layout: per row slot [evenL 640 | evenH 640 | oddL 640 | oddH 640]
// L = channels 0-7 (16 B), H = channels 8-15 (16 B). Address = base + idx*16,
// second chunk at +640 (immediate). 8-lane phase over consecutive idx covers
// 128 contiguous bytes -> conflict-free, no swizzle math.
#define ROWB 2560
#define POFF 1280                    // odd-parity offset within a row slot
#define CHNK 640                     // H-chunk offset within a parity

// load 16 halves (as 8 u32) from a parity sub-array
__device__ __forceinline__ void load16h(const char* pb, int idx, u32 h[8]) {
    const char* p = pb + (idx << 4);
    uint4 a = *(const uint4*)(p);
    uint4 b = *(const uint4*)(p + CHNK);
    h[0]=a.x; h[1]=a.y; h[2]=a.z; h[3]=a.w;
    h[4]=b.x; h[5]=b.y; h[6]=b.z; h[7]=b.w;
}

// ---- directional term for ONE center pixel (3x3 stencil inside the tile) ----
__device__ __forceinline__ float dirterm(const char* sF, const int* sLab,
                                         const int* __restrict__ labels,
                                         const int* __restrict__ dirs,
                                         const u32 cv[8], int srow, int xc,
                                         int pix) {
    float dt[NB]; bool mk[NB]; float S = 0.f;
#pragma unroll
    for (int k = 0; k < NB; k++) {
        int dik = dirs[(k * 2 + 0) * HWSZ + pix];
        int djk = dirs[(k * 2 + 1) * HWSZ + pix];
        int sl = srow + dik;
        int x  = xc + djk;
        u32 nv[8]; load16h(sF + sl * ROWB + (x & 1) * POFF, x >> 1, nv);
        dt[k] = dot16h(cv, nv);              // log2-scaled logit
        int lbn = sLab[sl * 80 + (x & 1) * 40 + (x >> 1)];
        mk[k] = (labels[k * HWSZ + pix] == lbn);
        S += mk[k] ? ex2f(dt[k]) : 0.f;
    }
    float logS = __logf(S + EPSV);
    float s = 0.f;
#pragma unroll
    for (int k = 0; k < NB; k++)
        s += mk[k] ? (logS - LN2F * dt[k]) : __int_as_float(0x7f800000);
    return s;
}

// ---------------------------------------------------------------------------
// Single fused kernel: halo fill normalizes raw fp32 features in-register,
// then local 11x11 + directional terms.
// Block = (n, 8 center rows, 64-col quarter). 128 threads, 2x2 quad each.
// ---------------------------------------------------------------------------
__global__ void __launch_bounds__(128, 4)
k_local(const float* __restrict__ feat, const int* __restrict__ labels,
        const int* __restrict__ dirs, float* __restrict__ out) {
    extern __shared__ char sm[];
    char* sF   = sm;                      // 18 * 2560 = 46080 B
    int*  sLab = (int*)(sm + 18 * ROWB);  // 18 * 80 ints = 5760 B

    const int bx  = blockIdx.x;           // 0..511
    const int n   = bx >> 7;
    const int rem = bx & 127;
    const int i0  = (rem >> 2) << 3;      // first center row (mult of 8)
    const int hq  = rem & 3;              // which 64-col quarter
    const int cb  = hq * 64 - 8;          // tile base col (global)
    const int t   = threadIdx.x;

    // ---- fill halo: 18 rows x 80 cols; normalize+quantize inline ----
    {
        const float* fbase = feat + (size_t)n * CH * HWSZ;
#pragma unroll 1
        for (int k = 0; k < 12; k++) {
            int lin = t + (k << 7);           // need 1440
            if (lin < 1440) {
                int rr = lin / 80;
                int x  = lin - rr * 80;
                int row = i0 - 5 + rr;
                int g   = cb + x;
                if ((unsigned)row < 256u && (unsigned)g < 256u) {
                    const float* p = fbase + (row << 8) + g;
                    float v[CH]; float ss = 0.f;
#pragma unroll
                    for (int c = 0; c < CH; c++) {
                        v[c] = p[(size_t)c * HWSZ];
                        ss = fmaf(v[c], v[c], ss);
                    }
                    float inv = 1.0f / fmaxf(sqrtf(ss), 1e-12f);
                    u32 h[8];
#pragma unroll
                    for (int c2 = 0; c2 < 8; c2++) {
                        __half2 hh = __floats2half2_rn(v[c2*2] * inv,
                                                       v[c2*2+1] * inv);
                        h[c2] = *(u32*)&hh;
                    }
                    char* dst = sF + rr * ROWB + (x & 1) * POFF + ((x >> 1) << 4);
                    *(uint4*)(dst)        = make_uint4(h[0], h[1], h[2], h[3]);
                    *(uint4*)(dst + CHNK) = make_uint4(h[4], h[5], h[6], h[7]);
                }
            }
        }
        const int* ls = labels + n * HWSZ;
#pragma unroll
        for (int k = 0; k < 12; k++) {
            int lin = t + (k << 7);           // need 1440
            if (lin < 1440) {
                int rr = lin / 80;
                int x  = lin - rr * 80;
                int row = i0 - 5 + rr;
                int g   = cb + x;
                bool ok = ((unsigned)row < 256u) && ((unsigned)g < 256u);
                sLab[rr * 80 + (x & 1) * 40 + (x >> 1)] =
                    ok ? ls[(row << 8) + g] : (int)0x80000000;
            }
        }
    }
    __syncthreads();

    const int rp = t >> 5;               // 0..3 (warp-uniform)
    const int cp = t & 31;
    const int tc = cp + 4;
    const int sA = 2 * rp + 5;
    const int sB = sA + 1;

    u32 cvAe[8], cvAo[8], cvBe[8], cvBo[8];
    load16h(sF + sA * ROWB,        tc, cvAe);
    load16h(sF + sA * ROWB + POFF, tc, cvAo);
    load16h(sF + sB * ROWB,        tc, cvBe);
    load16h(sF + sB * ROWB + POFF, tc, cvBo);
    __half2 kt = __floats2half2_rn(LOG2E_T, LOG2E_T);
    u32 kt2 = *(u32*)&kt;
    scale16h(cvAe, kt2); scale16h(cvAo, kt2);
    scale16h(cvBe, kt2); scale16h(cvBo, kt2);
    const int clAe = sLab[sA * 80 + tc];
    const int clAo = sLab[sA * 80 + 40 + tc];
    const int clBe = sLab[sB * 80 + tc];
    const int clBo = sLab[sB * 80 + 40 + tc];

    u64 SDAe = 0, SDAo = 0, SDBe = 0, SDBo = 0;   // packed {S, D}
    int MAe = 0, MAo = 0, MBe = 0, MBo = 0;

    // ================= v = 0 peel: A-centers only =================
    {
        int s   = 2 * rp;                  // slot 0..6
        int row = i0 - 5 + s;
        if (row >= 0) {                    // warp-uniform
            const char* rowE = sF + s * ROWB;
            const char* rowO = rowE + POFF;
            const int* labE = sLab + s * 80;
            const int* labO = labE + 40;
#pragma unroll
            for (int u = 0; u < 6; u++) {
                int e = cp + 2 + u;
                u32 nv[8]; load16h(rowE, e, nv);
                int lb = labE[e];
                float dAo = dot16h(cvAo, nv);
                float eAo = ex2f(dAo);
                if (lb == clAo) { SDAo = f2add(SDAo, pack2(eAo, dAo)); MAo++; }
                if (u != 5) {
                    float dAe = dot16h(cvAe, nv);
                    float eAe = ex2f(dAe);
                    if (lb == clAe) { SDAe = f2add(SDAe, pack2(eAe, dAe)); MAe++; }
                }
            }
#pragma unroll
            for (int u = 0; u < 6; u++) {
                int o = cp + 1 + u;
                u32 nv[8]; load16h(rowO, o, nv);
                int lb = labO[o];
                float dAe = dot16h(cvAe, nv);
                float eAe = ex2f(dAe);
                if (lb == clAe) { SDAe = f2add(SDAe, pack2(eAe, dAe)); MAe++; }
                if (u != 0) {
                    float dAo = dot16h(cvAo, nv);
                    float eAo = ex2f(dAo);
                    if (lb == clAo) { SDAo = f2add(SDAo, pack2(eAo, dAo)); MAo++; }
                }
            }
        }
    }

    // ================= main loop v = 1..10: all four centers =================
#pragma unroll 1
    for (int v = 1; v <= 10; v++) {
        int s   = 2 * rp + v;
        int row = i0 - 5 + s;
        if ((unsigned)row >= 256u) continue;   // warp-uniform
        const char* rowE = sF + s * ROWB;
        const char* rowO = rowE + POFF;
        const int* labE = sLab + s * 80;
        const int* labO = labE + 40;

        // even-pixel neighbors
#pragma unroll
        for (int u = 0; u < 6; u++) {
            int e = cp + 2 + u;
            u32 nv[8]; load16h(rowE, e, nv);
            int lb = labE[e];
            {
                float dAo = dot16h(cvAo, nv);
                float dBo = dot16h(cvBo, nv);
                float eAo = ex2f(dAo), eBo = ex2f(dBo);
                if (lb == clAo) { SDAo = f2add(SDAo, pack2(eAo, dAo)); MAo++; }
                if (lb == clBo) { SDBo = f2add(SDBo, pack2(eBo, dBo)); MBo++; }
            }
            if (u != 5) {
                float dAe = dot16h(cvAe, nv);
                float dBe = dot16h(cvBe, nv);
                float eAe = ex2f(dAe), eBe = ex2f(dBe);
                if (lb == clAe) { SDAe = f2add(SDAe, pack2(eAe, dAe)); MAe++; }
                if (lb == clBe) { SDBe = f2add(SDBe, pack2(eBe, dBe)); MBe++; }
            }
        }
        // odd-pixel neighbors
#pragma unroll
        for (int u = 0; u < 6; u++) {
            int o = cp + 1 + u;
            u32 nv[8]; load16h(rowO, o, nv);
            int lb = labO[o];
            {
                float dAe = dot16h(cvAe, nv);
                float dBe = dot16h(cvBe, nv);
                float eAe = ex2f(dAe), eBe = ex2f(dBe);
                if (lb == clAe) { SDAe = f2add(SDAe, pack2(eAe, dAe)); MAe++; }
                if (lb == clBe) { SDBe = f2add(SDBe, pack2(eBe, dBe)); MBe++; }
            }
            if (u != 0) {
                float dAo = dot16h(cvAo, nv);
                float dBo = dot16h(cvBo, nv);
                float eAo = ex2f(dAo), eBo = ex2f(dBo);
                if (lb == clAo) { SDAo = f2add(SDAo, pack2(eAo, dAo)); MAo++; }
                if (lb == clBo) { SDBo = f2add(SDBo, pack2(eBo, dBo)); MBo++; }
            }
        }
    }

    // ================= v = 11 peel: B-centers only =================
    {
        int s   = 2 * rp + 11;             // slot 11..17
        int row = i0 - 5 + s;
        if (row < 256) {                   // warp-uniform
            const char* rowE = sF + s * ROWB;
            const char* rowO = rowE + POFF;
            const int* labE = sLab + s * 80;
            const int* labO = labE + 40;
#pragma unroll
            for (int u = 0; u < 6; u++) {
                int e = cp + 2 + u;
                u32 nv[8]; load16h(rowE, e, nv);
                int lb = labE[e];
                float dBo = dot16h(cvBo, nv);
                float eBo = ex2f(dBo);
                if (lb == clBo) { SDBo = f2add(SDBo, pack2(eBo, dBo)); MBo++; }
                if (u != 5) {
                    float dBe = dot16h(cvBe, nv);
                    float eBe = ex2f(dBe);
                    if (lb == clBe) { SDBe = f2add(SDBe, pack2(eBe, dBe)); MBe++; }
                }
            }
#pragma unroll
            for (int u = 0; u < 6; u++) {
                int o = cp + 1 + u;
                u32 nv[8]; load16h(rowO, o, nv);
                int lb = labO[o];
                float dBe = dot16h(cvBe, nv);
                float eBe = ex2f(dBe);
                if (lb == clBe) { SDBe = f2add(SDBe, pack2(eBe, dBe)); MBe++; }
                if (u != 0) {
                    float dBo = dot16h(cvBo, nv);
                    float eBo = ex2f(dBo);
                    if (lb == clBo) { SDBo = f2add(SDBo, pack2(eBo, dBo)); MBo++; }
                }
            }
        }
    }

    float SAe, DAe, SAo, DAo, SBe, DBe, SBo, DBo;
    unpack2(SDAe, SAe, DAe);  unpack2(SDAo, SAo, DAo);
    unpack2(SDBe, SBe, DBe);  unpack2(SDBo, SBo, DBo);

    float cAe = fmaf((float)MAe, __logf(SAe + EPSV), -LN2F * DAe);
    float cAo = fmaf((float)MAo, __logf(SAo + EPSV), -LN2F * DAo);
    float cBe = fmaf((float)MBe, __logf(SBe + EPSV), -LN2F * DBe);
    float cBo = fmaf((float)MBo, __logf(SBo + EPSV), -LN2F * DBo);
    int ciA = i0 + 2 * rp, ciB = ciA + 1;
    int j0  = hq * 64 + 2 * cp, j1 = j0 + 1;
    float chA = (float)(11 - max(0, 5 - ciA) - max(0, ciA - 250));
    float chB = (float)(11 - max(0, 5 - ciB) - max(0, ciB - 250));
    float cw0 = (float)(11 - max(0, 5 - j0)  - max(0, j0  - 250));
    float cw1 = (float)(11 - max(0, 5 - j1)  - max(0, j1  - 250));
    float val = (cAe / (chA * cw0) + cAo / (chA * cw1)
               + cBe / (chB * cw0) + cBo / (chB * cw1)) * (1.0f / (4.0f * 65536.0f));

    // ---- directional term for this thread's 4 pixels (3x3 stencil in tile) --
    {
        float ds = dirterm(sF, sLab, labels, dirs, cvAe, sA, 2*cp + 8, (ciA << 8) + j0)
                 + dirterm(sF, sLab, labels, dirs, cvAo, sA, 2*cp + 9, (ciA << 8) + j1)
                 + dirterm(sF, sLab, labels, dirs, cvBe, sB, 2*cp + 8, (ciB << 8) + j0)
                 + dirterm(sF, sLab, labels, dirs, cvBo, sB, 2*cp + 9, (ciB << 8) + j1);
        val += ds * (1.0f / (16.0f * 65536.0f));
    }

    // ---- block reduce + last-finishing block folds the final sum ----
    __shared__ float wred[4];
    __shared__ bool  slast;
#pragma unroll
    for (int o = 16; o > 0; o >>= 1) val += __shfl_down_sync(0xffffffffu, val, o);
    if ((t & 31) == 0) wred[t >> 5] = val;
    __syncthreads();
    if (t == 0) {
        g_lp[bx] = (wred[0] + wred[1]) + (wred[2] + wred[3]);
        __threadfence();
        unsigned old = atomicAdd(&g_ctr, 1u);
        slast = (old == 511u);
    }
    __syncthreads();

    if (slast) {   // deterministic final reduction over 512 partials
        float v = g_lp[t] + g_lp[t + 128] + g_lp[t + 256] + g_lp[t + 384];
#pragma unroll
        for (int o = 16; o > 0; o >>= 1) v += __shfl_down_sync(0xffffffffu, v, o);
        if ((t & 31) == 0) wred[t >> 5] = v;
        __syncthreads();
        if (t == 0) {
            out[0] = (wred[0] + wred[1]) + (wred[2] + wred[3]);
            g_ctr = 0;   // reset for next graph replay
        }
    }
}

// ---------------------------------------------------------------------------
extern "C" void kernel_launch(void* const* d_in, const int* in_sizes, int n_in,
                              void* d_out, int out_size) {
    const float* feat   = (const float*)d_in[0];
    const int*   labels = (const int*)d_in[1];
    const int*   dirs   = (const int*)d_in[2];
    float* out = (float*)d_out;

    const int smem = 18 * ROWB + 18 * 80 * 4;   // 46080 + 5760 = 51840 B
    cudaFuncSetAttribute(k_local, cudaFuncAttributeMaxDynamicSharedMemorySize, smem);

    k_local<<<512, 128, smem>>>(feat, labels, dirs, out);
}